// round 1
// baseline (speedup 1.0000x reference)
#include <cuda_runtime.h>
#include <cstdint>

#define BDIM 8192
#define KTOP 3
#define MARGIN 0.8f
#define TAU 0.1f
#define NEG_FILL -50.0f

#define ROW_THREADS 256
#define VEC_PER_THREAD 8   // 8192 floats / 4 per float4 / 256 threads

__device__ float g_row_partial[BDIM];

__device__ __forceinline__ void insert3(float& t0, float& t1, float& t2, float x) {
    if (x > t2) {
        if (x > t0)      { t2 = t1; t1 = t0; t0 = x; }
        else if (x > t1) { t2 = t1; t1 = x; }
        else             { t2 = x; }
    }
}

__global__ __launch_bounds__(ROW_THREADS, 8)
void row_topk_kernel(const float* __restrict__ inp) {
    const int row = blockIdx.x;
    const float4* __restrict__ rp =
        reinterpret_cast<const float4*>(inp + (size_t)row * BDIM);
    const int t = threadIdx.x;

    float t0 = -1e30f, t1 = -1e30f, t2 = -1e30f;
    const int diag4 = row >> 2;      // which float4 holds the diagonal element
    const int diagl = row & 3;       // lane within that float4

    #pragma unroll
    for (int i = 0; i < VEC_PER_THREAD; i++) {
        const int p = t + i * ROW_THREADS;
        float4 v = rp[p];
        if (p == diag4) {
            // exclude the diagonal (positive) from hard-negative candidates
            if (diagl == 0) v.x = -1e30f;
            else if (diagl == 1) v.y = -1e30f;
            else if (diagl == 2) v.z = -1e30f;
            else v.w = -1e30f;
        }
        insert3(t0, t1, t2, v.x);
        insert3(t0, t1, t2, v.y);
        insert3(t0, t1, t2, v.z);
        insert3(t0, t1, t2, v.w);
    }

    // Warp-level merge of top-3 triples
    #pragma unroll
    for (int off = 16; off > 0; off >>= 1) {
        float a0 = __shfl_down_sync(0xFFFFFFFFu, t0, off);
        float a1 = __shfl_down_sync(0xFFFFFFFFu, t1, off);
        float a2 = __shfl_down_sync(0xFFFFFFFFu, t2, off);
        insert3(t0, t1, t2, a0);
        insert3(t0, t1, t2, a1);
        insert3(t0, t1, t2, a2);
    }

    __shared__ float sm[ROW_THREADS / 32][3];
    const int wid = t >> 5;
    const int lid = t & 31;
    if (lid == 0) { sm[wid][0] = t0; sm[wid][1] = t1; sm[wid][2] = t2; }
    __syncthreads();

    if (t == 0) {
        #pragma unroll
        for (int w = 1; w < ROW_THREADS / 32; w++) {
            insert3(t0, t1, t2, sm[w][0]);
            insert3(t0, t1, t2, sm[w][1]);
            insert3(t0, t1, t2, sm[w][2]);
        }
        // epilogue: hinge + softmax re-weighting over K=3 hard negatives
        const float sp = inp[(size_t)row * BDIM + row];

        float l0 = fmaxf(t0 - sp + MARGIN, 0.0f);
        float l1 = fmaxf(t1 - sp + MARGIN, 0.0f);
        float l2 = fmaxf(t2 - sp + MARGIN, 0.0f);

        float m0 = (l0 == 0.0f) ? NEG_FILL : t0;
        float m1 = (l1 == 0.0f) ? NEG_FILL : t1;
        float m2 = (l2 == 0.0f) ? NEG_FILL : t2;

        float mm = fmaxf(m0, fmaxf(m1, m2));
        // softmax(m / TAU) with TAU = 0.1 -> scale by 10
        float e0 = __expf((m0 - mm) * 10.0f);
        float e1 = __expf((m1 - mm) * 10.0f);
        float e2 = __expf((m2 - mm) * 10.0f);
        float s  = e0 + e1 + e2;

        g_row_partial[row] = (l0 * e0 + l1 * e1 + l2 * e2) / s;
    }
}

__global__ void reduce_kernel(float* __restrict__ out) {
    const int t = threadIdx.x;      // 1024 threads
    float acc = 0.0f;
    #pragma unroll
    for (int i = 0; i < BDIM / 1024; i++)
        acc += g_row_partial[t + i * 1024];

    #pragma unroll
    for (int off = 16; off > 0; off >>= 1)
        acc += __shfl_down_sync(0xFFFFFFFFu, acc, off);

    __shared__ float sm[32];
    const int wid = t >> 5;
    const int lid = t & 31;
    if (lid == 0) sm[wid] = acc;
    __syncthreads();

    if (t == 0) {
        float s = 0.0f;
        #pragma unroll
        for (int w = 0; w < 32; w++) s += sm[w];
        out[0] = s / (float)(BDIM * KTOP);
    }
}

extern "C" void kernel_launch(void* const* d_in, const int* in_sizes, int n_in,
                              void* d_out, int out_size) {
    const float* inp = (const float*)d_in[0];
    // d_in[1] is target == eye(B); masking reduces to diagonal exclusion, so unused.
    float* out = (float*)d_out;

    row_topk_kernel<<<BDIM, ROW_THREADS>>>(inp);
    reduce_kernel<<<1, 1024>>>(out);
}